// round 1
// baseline (speedup 1.0000x reference)
#include <cuda_runtime.h>
#include <cstdint>

// Problem constants
static constexpr int N_CELL  = 50000;
static constexpr int N_NET   = 10000;
static constexpr int N_GCELL = 20000;
static constexpr int E       = 100000;
static constexpr int D       = 32;

// Degree-counter layout (one big int array)
static constexpr int OFF_PINS_S   = 0;                       // size N_CELL
static constexpr int OFF_PINS_D   = OFF_PINS_S + N_CELL;     // N_NET
static constexpr int OFF_CON_S    = OFF_PINS_D + N_NET;      // N_GCELL
static constexpr int OFF_CON_D    = OFF_CON_S + N_GCELL;     // N_GCELL
static constexpr int OFF_PT_S     = OFF_CON_D + N_GCELL;     // N_CELL
static constexpr int OFF_PT_D     = OFF_PT_S + N_CELL;       // N_GCELL
static constexpr int OFF_PINNED_D = OFF_PT_D + N_GCELL;      // N_CELL
static constexpr int OFF_PF_D     = OFF_PINNED_D + N_CELL;   // N_CELL
static constexpr int DEG_TOTAL    = OFF_PF_D + N_CELL;       // 270000

// Scratch (__device__ globals: allocation-free rule)
__device__ int   g_deg[DEG_TOTAL];
__device__ float g_feat_pins[N_CELL * D];
__device__ float g_feat_pt[N_CELL * D];
__device__ float g_feat_connect[N_GCELL * D];
__device__ float g_P_net[(size_t)N_NET * 544];
__device__ float g_P_gcell[(size_t)N_GCELL * 544];

// ---------------------------------------------------------------------------
// Zero degree counters
__global__ void zero_deg_kernel() {
    int i = blockIdx.x * blockDim.x + threadIdx.x;
    if (i < DEG_TOTAL) g_deg[i] = 0;
}

// Initialize output with per-region bias sums (output then receives atomics)
__global__ void init_out_kernel(float* __restrict__ out,
                                const float* __restrict__ b_pinned,
                                const float* __restrict__ b_pf,
                                const float* __restrict__ b_pins,
                                const float* __restrict__ b_net,
                                const float* __restrict__ b_connect,
                                const float* __restrict__ b_pt) {
    int idx = blockIdx.x * blockDim.x + threadIdx.x;
    int total = (N_CELL + N_NET + N_GCELL) * D;
    if (idx >= total) return;
    int row = idx >> 5;
    int j = idx & 31;
    float v;
    if (row < N_CELL)                 v = b_pinned[j] + b_pf[j];
    else if (row < N_CELL + N_NET)    v = b_pins[j] + b_net[j];
    else                              v = b_connect[j] + b_pt[j];
    out[idx] = v;
}

// Count degrees for all 8 needed (index, n) pairs in one pass
__global__ void degree_kernel(const int* __restrict__ pins_src, const int* __restrict__ pins_dst,
                              const int* __restrict__ connect_src, const int* __restrict__ connect_dst,
                              const int* __restrict__ pt_src, const int* __restrict__ pt_dst,
                              const int* __restrict__ pinned_dst, const int* __restrict__ pf_dst) {
    int e = blockIdx.x * blockDim.x + threadIdx.x;
    if (e >= E) return;
    atomicAdd(&g_deg[OFF_PINS_S   + pins_src[e]], 1);
    atomicAdd(&g_deg[OFF_PINS_D   + pins_dst[e]], 1);
    atomicAdd(&g_deg[OFF_CON_S    + connect_src[e]], 1);
    atomicAdd(&g_deg[OFF_CON_D    + connect_dst[e]], 1);
    atomicAdd(&g_deg[OFF_PT_S     + pt_src[e]], 1);
    atomicAdd(&g_deg[OFF_PT_D     + pt_dst[e]], 1);
    atomicAdd(&g_deg[OFF_PINNED_D + pinned_dst[e]], 1);
    atomicAdd(&g_deg[OFF_PF_D     + pf_dst[e]], 1);
}

// ---------------------------------------------------------------------------
// Dense per-node 32x32 transform: out[n,:] = (X[n,:] * optional rsqrt(deg)) @ W
// W column j held in registers by lane j; x broadcast via shfl. 2 nodes/iter for ILP.
template <bool SCALE, bool ACCUM>
__global__ void transform32_kernel(const float* __restrict__ X,
                                   const float* __restrict__ Wg,
                                   const int* __restrict__ cnt,
                                   float* __restrict__ out, int n) {
    int lane = threadIdx.x & 31;
    int warp = (blockIdx.x * blockDim.x + threadIdx.x) >> 5;
    int nwarps = (gridDim.x * blockDim.x) >> 5;

    float w[32];
#pragma unroll
    for (int i = 0; i < 32; i++) w[i] = Wg[i * 32 + lane];

    for (int n0 = warp * 2; n0 < n; n0 += nwarps * 2) {
        int n1 = n0 + 1;
        bool has1 = (n1 < n);
        float x0 = X[n0 * 32 + lane];
        float x1 = has1 ? X[n1 * 32 + lane] : 0.0f;
        if (SCALE) {
            x0 *= rsqrtf((float)max(cnt[n0], 1));
            if (has1) x1 *= rsqrtf((float)max(cnt[n1], 1));
        }
        float a0 = 0.0f, a1 = 0.0f;
#pragma unroll
        for (int i = 0; i < 32; i++) {
            a0 = fmaf(__shfl_sync(0xffffffffu, x0, i), w[i], a0);
            a1 = fmaf(__shfl_sync(0xffffffffu, x1, i), w[i], a1);
        }
        if (ACCUM) out[n0 * 32 + lane] += a0; else out[n0 * 32 + lane] = a0;
        if (has1) { if (ACCUM) out[n1 * 32 + lane] += a1; else out[n1 * 32 + lane] = a1; }
    }
}

// ---------------------------------------------------------------------------
// P precompute: P[n, k*32+j] = sum_i X[n,i] * W_topo[k, i*32+j]  (k<16)
//               P[n, 512+j]  = sum_i X[n,i] * b_topo[i*32+j]
// GEMM (n,32)@(32,544), tiled: block = 32 nodes x 6 slots (gridDim.y groups of slots).
__global__ void pgemm_kernel(const float* __restrict__ X,
                             const float* __restrict__ W_topo,
                             const float* __restrict__ b_topo,
                             float* __restrict__ P, int n) {
    __shared__ float Wsm[32 * 192];   // 24 KB
    __shared__ float Asm[32 * 33];    // padded, 4.2 KB

    int g = blockIdx.y;               // 0,1,2
    int slot0 = g * 6;
    int ns = (g == 2) ? 5 : 6;        // group 2: slots 12..16 (16 = bias)

    // Stage W columns for this slot group
    for (int idx = threadIdx.x; idx < 32 * 192; idx += blockDim.x) {
        int i = idx / 192, c = idx % 192;
        int s = c >> 5, j = c & 31;
        int slot = slot0 + s;
        float v = 0.0f;
        if (slot < 16)       v = W_topo[slot * 1024 + i * 32 + j];
        else if (slot == 16) v = b_topo[i * 32 + j];
        Wsm[idx] = v;
    }
    // Stage A tile (32 nodes x 32)
    int n0 = blockIdx.x * 32;
    for (int idx = threadIdx.x; idx < 32 * 32; idx += blockDim.x) {
        int r = idx >> 5, cc = idx & 31;
        Asm[r * 33 + cc] = (n0 + r < n) ? X[(n0 + r) * 32 + cc] : 0.0f;
    }
    __syncthreads();

    int tx = threadIdx.x & 31;        // output col within slot
    int ty = threadIdx.x >> 5;        // 0..7 -> 4 nodes each
    float acc[4][6];
#pragma unroll
    for (int m = 0; m < 4; m++)
#pragma unroll
        for (int s = 0; s < 6; s++) acc[m][s] = 0.0f;

#pragma unroll
    for (int i = 0; i < 32; i++) {
        float a0 = Asm[(ty * 4 + 0) * 33 + i];
        float a1 = Asm[(ty * 4 + 1) * 33 + i];
        float a2 = Asm[(ty * 4 + 2) * 33 + i];
        float a3 = Asm[(ty * 4 + 3) * 33 + i];
#pragma unroll
        for (int s = 0; s < 6; s++) {
            float wv = Wsm[i * 192 + s * 32 + tx];
            acc[0][s] = fmaf(a0, wv, acc[0][s]);
            acc[1][s] = fmaf(a1, wv, acc[1][s]);
            acc[2][s] = fmaf(a2, wv, acc[2][s]);
            acc[3][s] = fmaf(a3, wv, acc[3][s]);
        }
    }

#pragma unroll
    for (int m = 0; m < 4; m++) {
        int node = n0 + ty * 4 + m;
        if (node >= n) break;
        for (int s = 0; s < ns; s++)
            P[(size_t)node * 544 + (slot0 + s) * 32 + tx] = acc[m][s];
    }
}

// ---------------------------------------------------------------------------
// GraphConv scatter: out[dst] += feat[src] * rsqrt(deg_dst)   (warp per edge)
__global__ void gc_scatter_kernel(const float* __restrict__ feat,
                                  const int* __restrict__ src, const int* __restrict__ dst,
                                  const int* __restrict__ cnt, float* __restrict__ out) {
    int t = blockIdx.x * blockDim.x + threadIdx.x;
    int e = t >> 5;
    if (e >= E) return;
    int lane = t & 31;
    int s = src[e], d = dst[e];
    float v = feat[s * 32 + lane];
    float sc = rsqrtf((float)max(cnt[d], 1));
    atomicAdd(&out[d * 32 + lane], v * sc);
}

// NNConv edge: out[dst] += (P_B[src] + sum_k ef[e,k]*P_k[src]) / deg_dst
__global__ void nn_edge_kernel(const float* __restrict__ P,
                               const float* __restrict__ ef,
                               const int* __restrict__ src, const int* __restrict__ dst,
                               const int* __restrict__ cnt, float* __restrict__ out) {
    int t = blockIdx.x * blockDim.x + threadIdx.x;
    int e = t >> 5;
    if (e >= E) return;
    int lane = t & 31;
    int s = src[e], d = dst[e];
    float ev = (lane < 16) ? ef[e * 16 + lane] : 0.0f;
    const float* Pr = P + (size_t)s * 544;
    float m = __ldg(&Pr[512 + lane]);          // bias slot
#pragma unroll
    for (int k = 0; k < 16; k++)
        m = fmaf(__shfl_sync(0xffffffffu, ev, k), __ldg(&Pr[k * 32 + lane]), m);
    float inv = 1.0f / (float)max(cnt[d], 1);
    atomicAdd(&out[d * 32 + lane], m * inv);
}

// ---------------------------------------------------------------------------
extern "C" void kernel_launch(void* const* d_in, const int* in_sizes, int n_in,
                              void* d_out, int out_size) {
    const float* node_feat   = (const float*)d_in[0];
    const float* net_feat    = (const float*)d_in[1];
    const float* pin_feat    = (const float*)d_in[2];
    const float* hanna_feat  = (const float*)d_in[3];
    const float* edge_feat   = (const float*)d_in[4];
    const int*   pins_src    = (const int*)d_in[5];
    const int*   pins_dst    = (const int*)d_in[6];
    const int*   pinned_src  = (const int*)d_in[7];
    const int*   pinned_dst  = (const int*)d_in[8];
    const int*   connect_src = (const int*)d_in[9];
    const int*   connect_dst = (const int*)d_in[10];
    const int*   pt_src      = (const int*)d_in[11];
    const int*   pt_dst      = (const int*)d_in[12];
    const int*   pf_src      = (const int*)d_in[13];
    const int*   pf_dst      = (const int*)d_in[14];
    const float* W_net       = (const float*)d_in[15];
    const float* b_net       = (const float*)d_in[16];
    const float* W_topo      = (const float*)d_in[17];
    const float* b_topo      = (const float*)d_in[18];
    const float* W_pins      = (const float*)d_in[19];
    const float* b_pins      = (const float*)d_in[20];
    const float* W_connect   = (const float*)d_in[21];
    const float* b_connect   = (const float*)d_in[22];
    const float* W_pt        = (const float*)d_in[23];
    const float* b_pt        = (const float*)d_in[24];
    const float* b_pinned    = (const float*)d_in[25];
    const float* b_pf        = (const float*)d_in[26];

    float* out       = (float*)d_out;
    float* out_net   = out + (size_t)N_CELL * D;
    float* out_gcell = out + (size_t)(N_CELL + N_NET) * D;

    void* p;
    cudaGetSymbolAddress(&p, g_deg);          int*   deg          = (int*)p;
    cudaGetSymbolAddress(&p, g_feat_pins);    float* feat_pins    = (float*)p;
    cudaGetSymbolAddress(&p, g_feat_pt);      float* feat_pt      = (float*)p;
    cudaGetSymbolAddress(&p, g_feat_connect); float* feat_connect = (float*)p;
    cudaGetSymbolAddress(&p, g_P_net);        float* P_net        = (float*)p;
    cudaGetSymbolAddress(&p, g_P_gcell);      float* P_gcell      = (float*)p;

    // 1) init
    zero_deg_kernel<<<(DEG_TOTAL + 255) / 256, 256>>>();
    init_out_kernel<<<((N_CELL + N_NET + N_GCELL) * D + 255) / 256, 256>>>(
        out, b_pinned, b_pf, b_pins, b_net, b_connect, b_pt);

    // 2) degrees
    degree_kernel<<<(E + 255) / 256, 256>>>(pins_src, pins_dst, connect_src, connect_dst,
                                            pt_src, pt_dst, pinned_dst, pf_dst);

    // 3) node transforms (GraphConv source-side norm folded in)
    const int TGRID = 592;
    transform32_kernel<true,  false><<<TGRID, 256>>>(node_feat,  W_pins,    deg + OFF_PINS_S, feat_pins,    N_CELL);
    transform32_kernel<true,  false><<<TGRID, 256>>>(node_feat,  W_pt,      deg + OFF_PT_S,   feat_pt,      N_CELL);
    transform32_kernel<true,  false><<<TGRID, 256>>>(hanna_feat, W_connect, deg + OFF_CON_S,  feat_connect, N_GCELL);
    transform32_kernel<false, true ><<<TGRID, 256>>>(net_feat,   W_net,     nullptr,          out_net,      N_NET);

    // 4) NNConv per-source-node factor P = [X@Wk ... X@B]
    pgemm_kernel<<<dim3((N_NET  + 31) / 32, 3), 256>>>(net_feat,   W_topo, b_topo, P_net,   N_NET);
    pgemm_kernel<<<dim3((N_GCELL + 31) / 32, 3), 256>>>(hanna_feat, W_topo, b_topo, P_gcell, N_GCELL);

    // 5) GraphConv scatters (dst-side norm folded into the atomic add)
    const int EGRID = (E * 32 + 255) / 256;
    gc_scatter_kernel<<<EGRID, 256>>>(feat_pins,    pins_src,    pins_dst,    deg + OFF_PINS_D, out_net);
    gc_scatter_kernel<<<EGRID, 256>>>(feat_connect, connect_src, connect_dst, deg + OFF_CON_D,  out_gcell);
    gc_scatter_kernel<<<EGRID, 256>>>(feat_pt,      pt_src,      pt_dst,      deg + OFF_PT_D,   out_gcell);

    // 6) NNConv edge phase (mean folded into the atomic add)
    nn_edge_kernel<<<EGRID, 256>>>(P_net,   pin_feat,  pinned_src, pinned_dst, deg + OFF_PINNED_D, out);
    nn_edge_kernel<<<EGRID, 256>>>(P_gcell, edge_feat, pf_src,     pf_dst,     deg + OFF_PF_D,     out);
}

// round 2
// speedup vs baseline: 1.4198x; 1.4198x over previous
#include <cuda_runtime.h>
#include <cuda_fp16.h>
#include <cstdint>

// Problem constants
static constexpr int N_CELL  = 50000;
static constexpr int N_NET   = 10000;
static constexpr int N_GCELL = 20000;
static constexpr int E       = 100000;
static constexpr int D       = 32;
static constexpr int N_PTOT  = N_NET + N_GCELL;          // 30000 P rows
static constexpr int OUT_TOTAL = (N_CELL + N_NET + N_GCELL) * D;   // 2.56M

// Degree-counter layout (one big int array)
static constexpr int OFF_PINS_S   = 0;                       // N_CELL
static constexpr int OFF_PINS_D   = OFF_PINS_S + N_CELL;     // N_NET
static constexpr int OFF_CON_S    = OFF_PINS_D + N_NET;      // N_GCELL
static constexpr int OFF_CON_D    = OFF_CON_S + N_GCELL;     // N_GCELL
static constexpr int OFF_PT_S     = OFF_CON_D + N_GCELL;     // N_CELL
static constexpr int OFF_PT_D     = OFF_PT_S + N_CELL;       // N_GCELL
static constexpr int OFF_PINNED_D = OFF_PT_D + N_GCELL;      // N_CELL
static constexpr int OFF_PF_D     = OFF_PINNED_D + N_CELL;   // N_CELL
static constexpr int DEG_TOTAL    = OFF_PF_D + N_CELL;       // 270000

// Scratch (__device__ globals: allocation-free rule)
__device__ int    g_deg[DEG_TOTAL];
__device__ float  g_feat_pins[N_CELL * D];
__device__ float  g_feat_pt[N_CELL * D];
__device__ float  g_feat_connect[N_GCELL * D];
__device__ __half g_P[(size_t)N_PTOT * 544];     // fp16 NNConv factor, 32.6 MB (L2-resident)

// ---------------------------------------------------------------------------
__device__ __forceinline__ void red_add_v4(float* addr, float x, float y, float z, float w) {
    asm volatile("red.global.add.v4.f32 [%0], {%1,%2,%3,%4};"
                 :: "l"(addr), "f"(x), "f"(y), "f"(z), "f"(w) : "memory");
}

__device__ __forceinline__ float4 ldh4(const __half* p) {
    uint2 u = __ldg(reinterpret_cast<const uint2*>(p));
    __half2 h0 = *reinterpret_cast<__half2*>(&u.x);
    __half2 h1 = *reinterpret_cast<__half2*>(&u.y);
    float2 f0 = __half22float2(h0);
    float2 f1 = __half22float2(h1);
    return make_float4(f0.x, f0.y, f1.x, f1.y);
}

// ---------------------------------------------------------------------------
// Fused init: zero degree counters + write per-region bias sums into out
__global__ void init_fused_kernel(float* __restrict__ out,
                                  const float* __restrict__ b_pinned,
                                  const float* __restrict__ b_pf,
                                  const float* __restrict__ b_pins,
                                  const float* __restrict__ b_net,
                                  const float* __restrict__ b_connect,
                                  const float* __restrict__ b_pt) {
    int idx = blockIdx.x * blockDim.x + threadIdx.x;
    if (idx < DEG_TOTAL) g_deg[idx] = 0;
    if (idx >= OUT_TOTAL) return;
    int row = idx >> 5;
    int j = idx & 31;
    float v;
    if (row < N_CELL)                 v = b_pinned[j] + b_pf[j];
    else if (row < N_CELL + N_NET)    v = b_pins[j] + b_net[j];
    else                              v = b_connect[j] + b_pt[j];
    out[idx] = v;
}

// Degrees for all 8 (index, n) pairs in one pass
__global__ void degree_kernel(const int* __restrict__ pins_src, const int* __restrict__ pins_dst,
                              const int* __restrict__ connect_src, const int* __restrict__ connect_dst,
                              const int* __restrict__ pt_src, const int* __restrict__ pt_dst,
                              const int* __restrict__ pinned_dst, const int* __restrict__ pf_dst) {
    int e = blockIdx.x * blockDim.x + threadIdx.x;
    if (e >= E) return;
    atomicAdd(&g_deg[OFF_PINS_S   + pins_src[e]], 1);
    atomicAdd(&g_deg[OFF_PINS_D   + pins_dst[e]], 1);
    atomicAdd(&g_deg[OFF_CON_S    + connect_src[e]], 1);
    atomicAdd(&g_deg[OFF_CON_D    + connect_dst[e]], 1);
    atomicAdd(&g_deg[OFF_PT_S     + pt_src[e]], 1);
    atomicAdd(&g_deg[OFF_PT_D     + pt_dst[e]], 1);
    atomicAdd(&g_deg[OFF_PINNED_D + pinned_dst[e]], 1);
    atomicAdd(&g_deg[OFF_PF_D     + pf_dst[e]], 1);
}

// ---------------------------------------------------------------------------
// Dual-W transform on node_feat: one read of X, two 32x32 products.
// feat_pins = rsqrt(deg_pins_s) * X @ W_pins ; feat_pt = rsqrt(deg_pt_s) * X @ W_pt
__global__ void transform_node_dual_kernel(const float* __restrict__ X,
                                           const float* __restrict__ W1,
                                           const float* __restrict__ W2,
                                           float* __restrict__ out1,
                                           float* __restrict__ out2) {
    int lane = threadIdx.x & 31;
    int warp = (blockIdx.x * blockDim.x + threadIdx.x) >> 5;
    int nwarps = (gridDim.x * blockDim.x) >> 5;

    float w1[32], w2[32];
#pragma unroll
    for (int i = 0; i < 32; i++) { w1[i] = W1[i * 32 + lane]; w2[i] = W2[i * 32 + lane]; }

    for (int n0 = warp * 2; n0 < N_CELL; n0 += nwarps * 2) {
        int n1 = n0 + 1;
        bool has1 = (n1 < N_CELL);
        float x0 = X[n0 * 32 + lane];
        float x1 = has1 ? X[n1 * 32 + lane] : 0.0f;
        float a0 = 0.f, b0 = 0.f, a1 = 0.f, b1 = 0.f;
#pragma unroll
        for (int i = 0; i < 32; i++) {
            float s0 = __shfl_sync(0xffffffffu, x0, i);
            float s1 = __shfl_sync(0xffffffffu, x1, i);
            a0 = fmaf(s0, w1[i], a0);
            b0 = fmaf(s0, w2[i], b0);
            a1 = fmaf(s1, w1[i], a1);
            b1 = fmaf(s1, w2[i], b1);
        }
        float sp0 = rsqrtf((float)max(g_deg[OFF_PINS_S + n0], 1));
        float st0 = rsqrtf((float)max(g_deg[OFF_PT_S + n0], 1));
        out1[n0 * 32 + lane] = a0 * sp0;
        out2[n0 * 32 + lane] = b0 * st0;
        if (has1) {
            float sp1 = rsqrtf((float)max(g_deg[OFF_PINS_S + n1], 1));
            float st1 = rsqrtf((float)max(g_deg[OFF_PT_S + n1], 1));
            out1[n1 * 32 + lane] = a1 * sp1;
            out2[n1 * 32 + lane] = b1 * st1;
        }
    }
}

// hanna -> feat_connect (scaled, write) and net -> out_net (accumulate), one launch
static constexpr int GH_BLOCKS = 400;
static constexpr int GN_BLOCKS = 200;
__global__ void transform_misc_kernel(const float* __restrict__ hanna,
                                      const float* __restrict__ Wc,
                                      const float* __restrict__ net,
                                      const float* __restrict__ Wn,
                                      float* __restrict__ feat_con,
                                      float* __restrict__ out_net) {
    int lane = threadIdx.x & 31;
    bool isH = (blockIdx.x < GH_BLOCKS);
    int bid = isH ? blockIdx.x : blockIdx.x - GH_BLOCKS;
    int nblocks = isH ? GH_BLOCKS : GN_BLOCKS;
    int warp = (bid * blockDim.x + threadIdx.x) >> 5;
    int nwarps = (nblocks * blockDim.x) >> 5;
    const float* X = isH ? hanna : net;
    const float* Wg = isH ? Wc : Wn;
    int n = isH ? N_GCELL : N_NET;

    float w[32];
#pragma unroll
    for (int i = 0; i < 32; i++) w[i] = Wg[i * 32 + lane];

    for (int n0 = warp * 2; n0 < n; n0 += nwarps * 2) {
        int n1 = n0 + 1;
        bool has1 = (n1 < n);
        float x0 = X[n0 * 32 + lane];
        float x1 = has1 ? X[n1 * 32 + lane] : 0.0f;
        float a0 = 0.f, a1 = 0.f;
#pragma unroll
        for (int i = 0; i < 32; i++) {
            a0 = fmaf(__shfl_sync(0xffffffffu, x0, i), w[i], a0);
            a1 = fmaf(__shfl_sync(0xffffffffu, x1, i), w[i], a1);
        }
        if (isH) {
            float s0 = rsqrtf((float)max(g_deg[OFF_CON_S + n0], 1));
            feat_con[n0 * 32 + lane] = a0 * s0;
            if (has1) {
                float s1 = rsqrtf((float)max(g_deg[OFF_CON_S + n1], 1));
                feat_con[n1 * 32 + lane] = a1 * s1;
            }
        } else {
            out_net[n0 * 32 + lane] += a0;
            if (has1) out_net[n1 * 32 + lane] += a1;
        }
    }
}

// ---------------------------------------------------------------------------
// P precompute over concatenated [net_feat ; hanna_feat] (30000 rows):
// P[n, s*32+j] = sum_i X[n,i] * W_topo[s, i*32+j]  (s<16),  P[n,512+j] = X[n,:]@b_topo col j
__global__ void pgemm_kernel(const float* __restrict__ net,
                             const float* __restrict__ hanna,
                             const float* __restrict__ W_topo,
                             const float* __restrict__ b_topo) {
    __shared__ float Wsm[32 * 192];   // 24 KB
    __shared__ float Asm[32 * 33];

    int g = blockIdx.y;               // 0,1,2
    int slot0 = g * 6;
    int ns = (g == 2) ? 5 : 6;

    for (int idx = threadIdx.x; idx < 32 * 192; idx += blockDim.x) {
        int i = idx / 192, c = idx % 192;
        int s = c >> 5, j = c & 31;
        int slot = slot0 + s;
        float v = 0.0f;
        if (slot < 16)       v = W_topo[slot * 1024 + i * 32 + j];
        else if (slot == 16) v = b_topo[i * 32 + j];
        Wsm[idx] = v;
    }
    int n0 = blockIdx.x * 32;
    for (int idx = threadIdx.x; idx < 32 * 32; idx += blockDim.x) {
        int r = idx >> 5, cc = idx & 31;
        int node = n0 + r;
        float v = 0.0f;
        if (node < N_NET) v = net[node * 32 + cc];
        else if (node < N_PTOT) v = hanna[(node - N_NET) * 32 + cc];
        Asm[r * 33 + cc] = v;
    }
    __syncthreads();

    int tx = threadIdx.x & 31;
    int ty = threadIdx.x >> 5;
    float acc[4][6];
#pragma unroll
    for (int m = 0; m < 4; m++)
#pragma unroll
        for (int s = 0; s < 6; s++) acc[m][s] = 0.0f;

#pragma unroll
    for (int i = 0; i < 32; i++) {
        float a0 = Asm[(ty * 4 + 0) * 33 + i];
        float a1 = Asm[(ty * 4 + 1) * 33 + i];
        float a2 = Asm[(ty * 4 + 2) * 33 + i];
        float a3 = Asm[(ty * 4 + 3) * 33 + i];
#pragma unroll
        for (int s = 0; s < 6; s++) {
            float wv = Wsm[i * 192 + s * 32 + tx];
            acc[0][s] = fmaf(a0, wv, acc[0][s]);
            acc[1][s] = fmaf(a1, wv, acc[1][s]);
            acc[2][s] = fmaf(a2, wv, acc[2][s]);
            acc[3][s] = fmaf(a3, wv, acc[3][s]);
        }
    }

#pragma unroll
    for (int m = 0; m < 4; m++) {
        int node = n0 + ty * 4 + m;
        if (node >= N_PTOT) break;
        for (int s = 0; s < ns; s++)
            g_P[(size_t)node * 544 + (slot0 + s) * 32 + tx] = __float2half_rn(acc[m][s]);
    }
}

// ---------------------------------------------------------------------------
// Fused GraphConv scatter: 3 relations per edge, quad-lane (8 lanes x float4 per edge),
// vector reductions. out[dst] += feat[src] * rsqrt(deg_dst)
__global__ void gc_fused_kernel(const int* __restrict__ pins_src, const int* __restrict__ pins_dst,
                                const int* __restrict__ con_src,  const int* __restrict__ con_dst,
                                const int* __restrict__ pt_src,   const int* __restrict__ pt_dst,
                                float* __restrict__ out_net, float* __restrict__ out_gcell) {
    int t = blockIdx.x * blockDim.x + threadIdx.x;
    int lane = t & 31;
    int e = ((t >> 5) << 2) + (lane >> 3);     // 4 edges per warp
    int q = lane & 7;
    if (e >= E) return;

    {   // pins: cell -> net
        int s = pins_src[e], d = pins_dst[e];
        float4 v = *reinterpret_cast<const float4*>(&g_feat_pins[s * 32 + q * 4]);
        float sc = rsqrtf((float)max(g_deg[OFF_PINS_D + d], 1));
        red_add_v4(out_net + d * 32 + q * 4, v.x * sc, v.y * sc, v.z * sc, v.w * sc);
    }
    {   // connect: gcell -> gcell
        int s = con_src[e], d = con_dst[e];
        float4 v = *reinterpret_cast<const float4*>(&g_feat_connect[s * 32 + q * 4]);
        float sc = rsqrtf((float)max(g_deg[OFF_CON_D + d], 1));
        red_add_v4(out_gcell + d * 32 + q * 4, v.x * sc, v.y * sc, v.z * sc, v.w * sc);
    }
    {   // point-to: cell -> gcell
        int s = pt_src[e], d = pt_dst[e];
        float4 v = *reinterpret_cast<const float4*>(&g_feat_pt[s * 32 + q * 4]);
        float sc = rsqrtf((float)max(g_deg[OFF_PT_D + d], 1));
        red_add_v4(out_gcell + d * 32 + q * 4, v.x * sc, v.y * sc, v.z * sc, v.w * sc);
    }
}

// Fused NNConv edge phase: both relations per edge, fp16 P gathers, vector reductions.
// out[dst] += (P_B[src] + sum_k ef[e,k] * P_k[src]) / deg_dst
__global__ void nn_fused_kernel(const float* __restrict__ efA,   // pin_feat  (pinned: net->cell)
                                const float* __restrict__ efB,   // edge_feat (pf: gcell->cell)
                                const int* __restrict__ srcA, const int* __restrict__ dstA,
                                const int* __restrict__ srcB, const int* __restrict__ dstB,
                                float* __restrict__ out_cell) {
    int t = blockIdx.x * blockDim.x + threadIdx.x;
    int lane = t & 31;
    int e = ((t >> 5) << 2) + (lane >> 3);
    int q = lane & 7;
    if (e >= E) return;
    int baseLane = lane & 24;   // (lane>>3)<<3

    int sA = srcA[e], dA = dstA[e];
    int sB = srcB[e] + N_NET, dB = dstB[e];
    float evA0 = efA[e * 16 + q],     evA1 = efA[e * 16 + 8 + q];
    float evB0 = efB[e * 16 + q],     evB1 = efB[e * 16 + 8 + q];

    const __half* PA = g_P + (size_t)sA * 544;
    const __half* PB = g_P + (size_t)sB * 544;

    float4 mA = ldh4(PA + 512 + q * 4);   // bias slot
    float4 mB = ldh4(PB + 512 + q * 4);

#pragma unroll
    for (int k = 0; k < 16; k++) {
        float cA = __shfl_sync(0xffffffffu, (k < 8) ? evA0 : evA1, baseLane + (k & 7));
        float cB = __shfl_sync(0xffffffffu, (k < 8) ? evB0 : evB1, baseLane + (k & 7));
        float4 pA = ldh4(PA + k * 32 + q * 4);
        float4 pB = ldh4(PB + k * 32 + q * 4);
        mA.x = fmaf(cA, pA.x, mA.x); mA.y = fmaf(cA, pA.y, mA.y);
        mA.z = fmaf(cA, pA.z, mA.z); mA.w = fmaf(cA, pA.w, mA.w);
        mB.x = fmaf(cB, pB.x, mB.x); mB.y = fmaf(cB, pB.y, mB.y);
        mB.z = fmaf(cB, pB.z, mB.z); mB.w = fmaf(cB, pB.w, mB.w);
    }

    float invA = 1.0f / (float)max(g_deg[OFF_PINNED_D + dA], 1);
    float invB = 1.0f / (float)max(g_deg[OFF_PF_D + dB], 1);
    red_add_v4(out_cell + dA * 32 + q * 4, mA.x * invA, mA.y * invA, mA.z * invA, mA.w * invA);
    red_add_v4(out_cell + dB * 32 + q * 4, mB.x * invB, mB.y * invB, mB.z * invB, mB.w * invB);
}

// ---------------------------------------------------------------------------
extern "C" void kernel_launch(void* const* d_in, const int* in_sizes, int n_in,
                              void* d_out, int out_size) {
    const float* node_feat   = (const float*)d_in[0];
    const float* net_feat    = (const float*)d_in[1];
    const float* pin_feat    = (const float*)d_in[2];
    const float* hanna_feat  = (const float*)d_in[3];
    const float* edge_feat   = (const float*)d_in[4];
    const int*   pins_src    = (const int*)d_in[5];
    const int*   pins_dst    = (const int*)d_in[6];
    const int*   pinned_src  = (const int*)d_in[7];
    const int*   pinned_dst  = (const int*)d_in[8];
    const int*   connect_src = (const int*)d_in[9];
    const int*   connect_dst = (const int*)d_in[10];
    const int*   pt_src      = (const int*)d_in[11];
    const int*   pt_dst      = (const int*)d_in[12];
    const int*   pf_src      = (const int*)d_in[13];
    const int*   pf_dst      = (const int*)d_in[14];
    const float* W_net       = (const float*)d_in[15];
    const float* b_net       = (const float*)d_in[16];
    const float* W_topo      = (const float*)d_in[17];
    const float* b_topo      = (const float*)d_in[18];
    const float* W_pins      = (const float*)d_in[19];
    const float* b_pins      = (const float*)d_in[20];
    const float* W_connect   = (const float*)d_in[21];
    const float* b_connect   = (const float*)d_in[22];
    const float* W_pt        = (const float*)d_in[23];
    const float* b_pt        = (const float*)d_in[24];
    const float* b_pinned    = (const float*)d_in[25];
    const float* b_pf        = (const float*)d_in[26];

    float* out       = (float*)d_out;
    float* out_net   = out + (size_t)N_CELL * D;
    float* out_gcell = out + (size_t)(N_CELL + N_NET) * D;

    void* p;
    cudaGetSymbolAddress(&p, g_feat_pins);    float* feat_pins    = (float*)p;
    cudaGetSymbolAddress(&p, g_feat_pt);      float* feat_pt      = (float*)p;
    cudaGetSymbolAddress(&p, g_feat_connect); float* feat_connect = (float*)p;

    // 1) fused init (zero degrees + bias-sum output init)
    init_fused_kernel<<<(OUT_TOTAL + 255) / 256, 256>>>(out, b_pinned, b_pf, b_pins, b_net, b_connect, b_pt);

    // 2) degrees
    degree_kernel<<<(E + 255) / 256, 256>>>(pins_src, pins_dst, connect_src, connect_dst,
                                            pt_src, pt_dst, pinned_dst, pf_dst);

    // 3) NNConv per-source factor P (independent of degrees)
    pgemm_kernel<<<dim3((N_PTOT + 31) / 32, 3), 256>>>(net_feat, hanna_feat, W_topo, b_topo);

    // 4) node transforms
    transform_node_dual_kernel<<<592, 256>>>(node_feat, W_pins, W_pt, feat_pins, feat_pt);
    transform_misc_kernel<<<GH_BLOCKS + GN_BLOCKS, 256>>>(hanna_feat, W_connect, net_feat, W_net,
                                                          feat_connect, out_net);

    // 5) fused GraphConv scatters (4 edges/warp, v4 reductions)
    const int EGRID = (E / 4 * 32 + 255) / 256;   // 3125 blocks
    gc_fused_kernel<<<EGRID, 256>>>(pins_src, pins_dst, connect_src, connect_dst,
                                    pt_src, pt_dst, out_net, out_gcell);

    // 6) fused NNConv edge phase
    nn_fused_kernel<<<EGRID, 256>>>(pin_feat, edge_feat, pinned_src, pinned_dst,
                                    pf_src, pf_dst, out);
}

// round 3
// speedup vs baseline: 1.7932x; 1.2630x over previous
#include <cuda_runtime.h>
#include <cuda_fp16.h>
#include <cstdint>

// Problem constants
static constexpr int N_CELL  = 50000;
static constexpr int N_NET   = 10000;
static constexpr int N_GCELL = 20000;
static constexpr int E       = 100000;
static constexpr int D       = 32;
static constexpr int N_PTOT  = N_NET + N_GCELL;                    // 30000 P rows
static constexpr int OUT_TOTAL = (N_CELL + N_NET + N_GCELL) * D;   // 2.56M

// Degree-counter layout
static constexpr int OFF_PINS_S   = 0;
static constexpr int OFF_PINS_D   = OFF_PINS_S + N_CELL;
static constexpr int OFF_CON_S    = OFF_PINS_D + N_NET;
static constexpr int OFF_CON_D    = OFF_CON_S + N_GCELL;
static constexpr int OFF_PT_S     = OFF_CON_D + N_GCELL;
static constexpr int OFF_PT_D     = OFF_PT_S + N_CELL;
static constexpr int OFF_PINNED_D = OFF_PT_D + N_GCELL;
static constexpr int OFF_PF_D     = OFF_PINNED_D + N_CELL;
static constexpr int DEG_TOTAL    = OFF_PF_D + N_CELL;             // 270000

// Scratch
__device__ int    g_deg[DEG_TOTAL];
__device__ float  g_feat_pins[N_CELL * D];
__device__ float  g_feat_pt[N_CELL * D];
__device__ float  g_feat_connect[N_GCELL * D];
__device__ __half g_P[(size_t)N_PTOT * 544];     // fp16 NNConv factor (32.6 MB, L2-resident)

// ---------------------------------------------------------------------------
// f32x2 packed-FMA helpers (Blackwell FFMA2 — 2x fp32 FMA throughput)
typedef unsigned long long ull;
__device__ __forceinline__ ull f2pack(float lo, float hi) {
    ull r; asm("mov.b64 %0, {%1,%2};" : "=l"(r) : "f"(lo), "f"(hi)); return r;
}
__device__ __forceinline__ void f2unpack(ull v, float& lo, float& hi) {
    asm("mov.b64 {%0,%1}, %2;" : "=f"(lo), "=f"(hi) : "l"(v));
}
__device__ __forceinline__ ull ffma2(ull a, ull b, ull c) {
    ull d; asm("fma.rn.f32x2 %0, %1, %2, %3;" : "=l"(d) : "l"(a), "l"(b), "l"(c)); return d;
}

__device__ __forceinline__ void red_add_v4(float* addr, float x, float y, float z, float w) {
    asm volatile("red.global.add.v4.f32 [%0], {%1,%2,%3,%4};"
                 :: "l"(addr), "f"(x), "f"(y), "f"(z), "f"(w) : "memory");
}

__device__ __forceinline__ float4 ldh4(const __half* p) {
    uint2 u = __ldg(reinterpret_cast<const uint2*>(p));
    __half2 h0 = *reinterpret_cast<__half2*>(&u.x);
    __half2 h1 = *reinterpret_cast<__half2*>(&u.y);
    float2 f0 = __half22float2(h0);
    float2 f1 = __half22float2(h1);
    return make_float4(f0.x, f0.y, f1.x, f1.y);
}

// ---------------------------------------------------------------------------
// Fused init: zero degree counters + write per-region bias sums into out
__global__ void init_fused_kernel(float* __restrict__ out,
                                  const float* __restrict__ b_pinned,
                                  const float* __restrict__ b_pf,
                                  const float* __restrict__ b_pins,
                                  const float* __restrict__ b_net,
                                  const float* __restrict__ b_connect,
                                  const float* __restrict__ b_pt) {
    int idx = blockIdx.x * blockDim.x + threadIdx.x;
    if (idx < DEG_TOTAL) g_deg[idx] = 0;
    if (idx >= OUT_TOTAL) return;
    int row = idx >> 5;
    int j = idx & 31;
    float v;
    if (row < N_CELL)                 v = b_pinned[j] + b_pf[j];
    else if (row < N_CELL + N_NET)    v = b_pins[j] + b_net[j];
    else                              v = b_connect[j] + b_pt[j];
    out[idx] = v;
}

// Degrees for all 8 (index, n) pairs in one pass
__global__ void degree_kernel(const int* __restrict__ pins_src, const int* __restrict__ pins_dst,
                              const int* __restrict__ connect_src, const int* __restrict__ connect_dst,
                              const int* __restrict__ pt_src, const int* __restrict__ pt_dst,
                              const int* __restrict__ pinned_dst, const int* __restrict__ pf_dst) {
    int e = blockIdx.x * blockDim.x + threadIdx.x;
    if (e >= E) return;
    atomicAdd(&g_deg[OFF_PINS_S   + pins_src[e]], 1);
    atomicAdd(&g_deg[OFF_PINS_D   + pins_dst[e]], 1);
    atomicAdd(&g_deg[OFF_CON_S    + connect_src[e]], 1);
    atomicAdd(&g_deg[OFF_CON_D    + connect_dst[e]], 1);
    atomicAdd(&g_deg[OFF_PT_S     + pt_src[e]], 1);
    atomicAdd(&g_deg[OFF_PT_D     + pt_dst[e]], 1);
    atomicAdd(&g_deg[OFF_PINNED_D + pinned_dst[e]], 1);
    atomicAdd(&g_deg[OFF_PF_D     + pf_dst[e]], 1);
}

// ---------------------------------------------------------------------------
// Unified dense mega-kernel: every 32-deep GEMM in the model, with f32x2 FMA.
// Jobs (dispatched by blockIdx.x range; each block does a 32-row tile):
//   0: P-GEMM [net;hanna](30000x32) @ W_topo-slots. 5 col groups:
//      grp 0..3 -> 128 cols (4 W_topo slots), grp 4 -> 32 cols (b_topo slot).
//   1: dual node transform: node_feat @ [W_pins | W_pt] (64 cols), per-half scaled.
//   2: hanna @ W_connect (32 cols), scaled.
//   3: net @ W_net (32 cols), accumulated into out_net.
static constexpr int NT_P    = (N_PTOT + 31) / 32;     // 938
static constexpr int NB_P    = NT_P * 5;               // 4690
static constexpr int NT_DUAL = (N_CELL + 31) / 32;     // 1563
static constexpr int NT_CON  = (N_GCELL + 31) / 32;    // 625
static constexpr int NT_NET  = (N_NET + 31) / 32;      // 313
static constexpr int NB_TOTAL = NB_P + NT_DUAL + NT_CON + NT_NET;

__global__ __launch_bounds__(256) void dense_kernel(
        const float* __restrict__ node_feat,
        const float* __restrict__ net_feat,
        const float* __restrict__ hanna_feat,
        const float* __restrict__ W_topo, const float* __restrict__ b_topo,
        const float* __restrict__ W_pins, const float* __restrict__ W_pt,
        const float* __restrict__ W_connect, const float* __restrict__ W_net,
        float* __restrict__ out_net) {
    __shared__ ull Asm2[32 * 33];    // (a,a) packed A tile
    __shared__ ull Wsm2[32 * 64];    // paired W columns

    int bid = blockIdx.x;
    int tid = threadIdx.x;

    int jobtype, tile, grp = 0;
    if (bid < NB_P)                       { jobtype = 0; tile = bid / 5; grp = bid % 5; }
    else if (bid < NB_P + NT_DUAL)        { jobtype = 1; tile = bid - NB_P; }
    else if (bid < NB_P + NT_DUAL + NT_CON){ jobtype = 2; tile = bid - NB_P - NT_DUAL; }
    else                                  { jobtype = 3; tile = bid - NB_P - NT_DUAL - NT_CON; }

    int n0 = tile * 32;
    int nrows = (jobtype == 0) ? N_PTOT : (jobtype == 1) ? N_CELL : (jobtype == 2) ? N_GCELL : N_NET;

    // ---- stage A (packed (a,a)) ----
    for (int idx = tid; idx < 32 * 32; idx += 256) {
        int r = idx >> 5, c = idx & 31;
        int node = n0 + r;
        float v = 0.0f;
        if (node < nrows) {
            if (jobtype == 0)      v = (node < N_NET) ? net_feat[node * 32 + c]
                                                      : hanna_feat[(node - N_NET) * 32 + c];
            else if (jobtype == 1) v = node_feat[node * 32 + c];
            else if (jobtype == 2) v = hanna_feat[node * 32 + c];
            else                   v = net_feat[node * 32 + c];
        }
        Asm2[r * 33 + c] = f2pack(v, v);
    }

    // ---- stage W pairs ----
    int npairs = (jobtype == 0) ? ((grp < 4) ? 64 : 16) : (jobtype == 1) ? 32 : 16;
    for (int idx = tid; idx < 32 * npairs; idx += 256) {
        int i = idx / npairs, p = idx % npairs;
        float2 w;
        if (jobtype == 0) {
            if (grp < 4) {
                int slot = grp * 4 + (p >> 4);
                w = *(const float2*)&W_topo[slot * 1024 + i * 32 + (p & 15) * 2];
            } else {
                w = *(const float2*)&b_topo[i * 32 + p * 2];
            }
        } else if (jobtype == 1) {
            w = (p < 16) ? *(const float2*)&W_pins[i * 32 + p * 2]
                         : *(const float2*)&W_pt[i * 32 + (p - 16) * 2];
        } else if (jobtype == 2) {
            w = *(const float2*)&W_connect[i * 32 + p * 2];
        } else {
            w = *(const float2*)&W_net[i * 32 + p * 2];
        }
        Wsm2[i * npairs + p] = f2pack(w.x, w.y);
    }
    __syncthreads();

    // ---- compute + store ----
    if (jobtype == 0 && grp < 4) {
        // 128 cols: thread = colpair tx & tx+32, rows ty*4..+3
        int tx = tid & 31, ty = tid >> 5;
        ull acc[4][2] = {};
#pragma unroll
        for (int i = 0; i < 32; i++) {
            ull w0 = Wsm2[i * 64 + tx];
            ull w1 = Wsm2[i * 64 + 32 + tx];
#pragma unroll
            for (int r = 0; r < 4; r++) {
                ull a = Asm2[(ty * 4 + r) * 33 + i];
                acc[r][0] = ffma2(a, w0, acc[r][0]);
                acc[r][1] = ffma2(a, w1, acc[r][1]);
            }
        }
#pragma unroll
        for (int r = 0; r < 4; r++) {
            int node = n0 + ty * 4 + r;
            if (node >= N_PTOT) break;
            float lo, hi;
            f2unpack(acc[r][0], lo, hi);
            *(__half2*)&g_P[(size_t)node * 544 + grp * 128 + tx * 2] = __floats2half2_rn(lo, hi);
            f2unpack(acc[r][1], lo, hi);
            *(__half2*)&g_P[(size_t)node * 544 + grp * 128 + 64 + tx * 2] = __floats2half2_rn(lo, hi);
        }
    } else if (jobtype == 1) {
        // 64 cols: colpair tx (tx<16 -> W_pins half, else W_pt half), rows ty*4..+3
        int tx = tid & 31, ty = tid >> 5;
        ull acc[4] = {};
#pragma unroll
        for (int i = 0; i < 32; i++) {
            ull w = Wsm2[i * 32 + tx];
#pragma unroll
            for (int r = 0; r < 4; r++)
                acc[r] = ffma2(Asm2[(ty * 4 + r) * 33 + i], w, acc[r]);
        }
#pragma unroll
        for (int r = 0; r < 4; r++) {
            int node = n0 + ty * 4 + r;
            if (node >= N_CELL) break;
            float lo, hi;
            f2unpack(acc[r], lo, hi);
            if (tx < 16) {
                float s = rsqrtf((float)max(g_deg[OFF_PINS_S + node], 1));
                *(float2*)&g_feat_pins[node * 32 + tx * 2] = make_float2(lo * s, hi * s);
            } else {
                float s = rsqrtf((float)max(g_deg[OFF_PT_S + node], 1));
                *(float2*)&g_feat_pt[node * 32 + (tx - 16) * 2] = make_float2(lo * s, hi * s);
            }
        }
    } else {
        // 32 cols (P bias group / connect / net): colpair tx(0..15), rows tyy*2..+1
        int tx = tid & 15, tyy = tid >> 4;
        ull acc[2] = {};
#pragma unroll
        for (int i = 0; i < 32; i++) {
            ull w = Wsm2[i * 16 + tx];
            acc[0] = ffma2(Asm2[(tyy * 2 + 0) * 33 + i], w, acc[0]);
            acc[1] = ffma2(Asm2[(tyy * 2 + 1) * 33 + i], w, acc[1]);
        }
#pragma unroll
        for (int r = 0; r < 2; r++) {
            int node = n0 + tyy * 2 + r;
            if (node >= nrows) break;
            float lo, hi;
            f2unpack(acc[r], lo, hi);
            if (jobtype == 0) {
                *(__half2*)&g_P[(size_t)node * 544 + 512 + tx * 2] = __floats2half2_rn(lo, hi);
            } else if (jobtype == 2) {
                float s = rsqrtf((float)max(g_deg[OFF_CON_S + node], 1));
                *(float2*)&g_feat_connect[node * 32 + tx * 2] = make_float2(lo * s, hi * s);
            } else {
                float2* o = (float2*)&out_net[node * 32 + tx * 2];
                float2 cur = *o;
                *o = make_float2(cur.x + lo, cur.y + hi);
            }
        }
    }
}

// ---------------------------------------------------------------------------
// Edge mega-kernel: all 5 relations, 4 edges/warp (8 lanes x float4 per edge).
__global__ __launch_bounds__(256) void edge_kernel(
        const int* __restrict__ pins_src, const int* __restrict__ pins_dst,
        const int* __restrict__ con_src,  const int* __restrict__ con_dst,
        const int* __restrict__ pt_src,   const int* __restrict__ pt_dst,
        const int* __restrict__ pinned_src, const int* __restrict__ pinned_dst,
        const int* __restrict__ pf_src,   const int* __restrict__ pf_dst,
        const float* __restrict__ pin_feat, const float* __restrict__ edge_feat,
        float* __restrict__ out_cell, float* __restrict__ out_net, float* __restrict__ out_gcell) {
    int t = blockIdx.x * blockDim.x + threadIdx.x;
    int lane = t & 31;
    int e = ((t >> 5) << 2) + (lane >> 3);     // 4 edges per warp
    int q = lane & 7;
    if (e >= E) return;
    int baseLane = lane & 24;

    // --- GraphConv scatters: out[dst] += feat[src] * rsqrt(deg_dst) ---
    {
        int s = pins_src[e], d = pins_dst[e];
        float4 v = *reinterpret_cast<const float4*>(&g_feat_pins[s * 32 + q * 4]);
        float sc = rsqrtf((float)max(g_deg[OFF_PINS_D + d], 1));
        red_add_v4(out_net + d * 32 + q * 4, v.x * sc, v.y * sc, v.z * sc, v.w * sc);
    }
    {
        int s = con_src[e], d = con_dst[e];
        float4 v = *reinterpret_cast<const float4*>(&g_feat_connect[s * 32 + q * 4]);
        float sc = rsqrtf((float)max(g_deg[OFF_CON_D + d], 1));
        red_add_v4(out_gcell + d * 32 + q * 4, v.x * sc, v.y * sc, v.z * sc, v.w * sc);
    }
    {
        int s = pt_src[e], d = pt_dst[e];
        float4 v = *reinterpret_cast<const float4*>(&g_feat_pt[s * 32 + q * 4]);
        float sc = rsqrtf((float)max(g_deg[OFF_PT_D + d], 1));
        red_add_v4(out_gcell + d * 32 + q * 4, v.x * sc, v.y * sc, v.z * sc, v.w * sc);
    }

    // --- NNConv edges: out[dst] += (P_B[src] + sum_k ef[e,k]*P_k[src]) / deg_dst ---
    {
        int sA = pinned_src[e], dA = pinned_dst[e];
        int sB = pf_src[e] + N_NET, dB = pf_dst[e];
        float evA0 = pin_feat[e * 16 + q],  evA1 = pin_feat[e * 16 + 8 + q];
        float evB0 = edge_feat[e * 16 + q], evB1 = edge_feat[e * 16 + 8 + q];

        const __half* PA = g_P + (size_t)sA * 544;
        const __half* PB = g_P + (size_t)sB * 544;

        float4 mA = ldh4(PA + 512 + q * 4);
        float4 mB = ldh4(PB + 512 + q * 4);

#pragma unroll
        for (int k = 0; k < 16; k++) {
            float cA = __shfl_sync(0xffffffffu, (k < 8) ? evA0 : evA1, baseLane + (k & 7));
            float cB = __shfl_sync(0xffffffffu, (k < 8) ? evB0 : evB1, baseLane + (k & 7));
            float4 pA = ldh4(PA + k * 32 + q * 4);
            float4 pB = ldh4(PB + k * 32 + q * 4);
            mA.x = fmaf(cA, pA.x, mA.x); mA.y = fmaf(cA, pA.y, mA.y);
            mA.z = fmaf(cA, pA.z, mA.z); mA.w = fmaf(cA, pA.w, mA.w);
            mB.x = fmaf(cB, pB.x, mB.x); mB.y = fmaf(cB, pB.y, mB.y);
            mB.z = fmaf(cB, pB.z, mB.z); mB.w = fmaf(cB, pB.w, mB.w);
        }

        float invA = 1.0f / (float)max(g_deg[OFF_PINNED_D + dA], 1);
        float invB = 1.0f / (float)max(g_deg[OFF_PF_D + dB], 1);
        red_add_v4(out_cell + dA * 32 + q * 4, mA.x * invA, mA.y * invA, mA.z * invA, mA.w * invA);
        red_add_v4(out_cell + dB * 32 + q * 4, mB.x * invB, mB.y * invB, mB.z * invB, mB.w * invB);
    }
}

// ---------------------------------------------------------------------------
extern "C" void kernel_launch(void* const* d_in, const int* in_sizes, int n_in,
                              void* d_out, int out_size) {
    const float* node_feat   = (const float*)d_in[0];
    const float* net_feat    = (const float*)d_in[1];
    const float* pin_feat    = (const float*)d_in[2];
    const float* hanna_feat  = (const float*)d_in[3];
    const float* edge_feat   = (const float*)d_in[4];
    const int*   pins_src    = (const int*)d_in[5];
    const int*   pins_dst    = (const int*)d_in[6];
    const int*   pinned_src  = (const int*)d_in[7];
    const int*   pinned_dst  = (const int*)d_in[8];
    const int*   connect_src = (const int*)d_in[9];
    const int*   connect_dst = (const int*)d_in[10];
    const int*   pt_src      = (const int*)d_in[11];
    const int*   pt_dst      = (const int*)d_in[12];
    const int*   pf_src      = (const int*)d_in[13];
    const int*   pf_dst      = (const int*)d_in[14];
    const float* W_net       = (const float*)d_in[15];
    const float* b_net       = (const float*)d_in[16];
    const float* W_topo      = (const float*)d_in[17];
    const float* b_topo      = (const float*)d_in[18];
    const float* W_pins      = (const float*)d_in[19];
    const float* b_pins      = (const float*)d_in[20];
    const float* W_connect   = (const float*)d_in[21];
    const float* b_connect   = (const float*)d_in[22];
    const float* W_pt        = (const float*)d_in[23];
    const float* b_pt        = (const float*)d_in[24];
    const float* b_pinned    = (const float*)d_in[25];
    const float* b_pf        = (const float*)d_in[26];

    float* out       = (float*)d_out;
    float* out_net   = out + (size_t)N_CELL * D;
    float* out_gcell = out + (size_t)(N_CELL + N_NET) * D;

    // 1) fused init (zero degrees + bias-sum output init)
    init_fused_kernel<<<(OUT_TOTAL + 255) / 256, 256>>>(out, b_pinned, b_pf, b_pins, b_net, b_connect, b_pt);

    // 2) degrees
    degree_kernel<<<(E + 255) / 256, 256>>>(pins_src, pins_dst, connect_src, connect_dst,
                                            pt_src, pt_dst, pinned_dst, pf_dst);

    // 3) all dense GEMMs in one launch (f32x2 packed FMA)
    dense_kernel<<<NB_TOTAL, 256>>>(node_feat, net_feat, hanna_feat,
                                    W_topo, b_topo, W_pins, W_pt, W_connect, W_net, out_net);

    // 4) all 5 edge relations in one launch
    const int EGRID = (E / 4 * 32 + 255) / 256;   // 3125 blocks
    edge_kernel<<<EGRID, 256>>>(pins_src, pins_dst, connect_src, connect_dst,
                                pt_src, pt_dst, pinned_src, pinned_dst, pf_src, pf_dst,
                                pin_feat, edge_feat, out, out_net, out_gcell);
}